// round 10
// baseline (speedup 1.0000x reference)
#include <cuda_runtime.h>

#define T_   100
#define R_   300
#define S_   500
#define P_   8
#define RC_  50
#define LOG2PI_ 1.8378770664093453f
#define DEATH_RATE_ 0.02f

#define BM 64
#define BN 128
#define BK 16
#define GT 128   // threads per GEMM block; micro tile 8x8 (i-packed f32x2)

#define NSLOTS 16384
#define SLOT_GEMM2  0      // 1980 blocks
#define SLOT_MISC   4096   // 3750 blocks
#define SLOT_STRAIN 8192   // 5000 blocks

// ---- scratch (device globals; no allocation allowed) ----
__device__ float  g_transitT[R_ * R_];                    // transitT[R][r] = transit[r][R]
__device__ float  g_mut[S_ * S_];                         // mut[s][S]
__device__ float  g_pred1[(size_t)(T_ - 1) * R_ * S_];    // 59.4 MB
__device__ double g_part[NSLOTS];

// packed f32x2 helpers (sm_103a) -------------------------------------------
__device__ __forceinline__ unsigned long long pack_dup_f32x2(float v) {
    unsigned long long d;
    unsigned int u = __float_as_uint(v);
    asm("mov.b64 %0, {%1, %1};" : "=l"(d) : "r"(u));
    return d;
}
__device__ __forceinline__ void fma_f32x2(unsigned long long& acc,
                                          unsigned long long a,
                                          unsigned long long b) {
    asm("fma.rn.f32x2 %0, %1, %2, %0;" : "+l"(acc) : "l"(a), "l"(b));
}

// ============================================================
__global__ void k_init() {
    int i = blockIdx.x * blockDim.x + threadIdx.x;
    if (i < NSLOTS) g_part[i] = 0.0;
}

__global__ void k_prep(const float* __restrict__ td, const float* __restrict__ tr,
                       const float* __restrict__ mm, const float* __restrict__ mrp) {
    int i = blockIdx.x * blockDim.x + threadIdx.x;
    if (i < R_ * R_) {
        int Rr = i / R_, r = i - Rr * R_;
        float a = 0.f;
#pragma unroll
        for (int p = 0; p < P_; p++)
            a += td[((size_t)r * R_ + Rr) * P_ + p] * tr[p];
        g_transitT[i] = a;   // = transit[r][Rr]
    }
    if (i < S_ * S_) {
        int s = i / S_, sn = i - s * S_;
        g_mut[i] = (s == sn ? 1.f : 0.f) + (*mrp) * mm[i];
    }
}

// ============================================================
// Compute step on one smem tile: 8(m) x 8(n) micro-tile, m-pairs packed f32x2.
// tx in 0..15 selects 8 n's; ty in 0..7 selects 8 m's.
__device__ __forceinline__ void mm_tile(const float (*As)[BM + 4], const float (*Bs)[BN],
                                        int tx, int ty, unsigned long long acc2[4][8]) {
#pragma unroll
    for (int k = 0; k < BK; k++) {
        ulonglong2 ap0 = *(const ulonglong2*)&As[k][ty * 8];      // m-pairs (0,1),(2,3)
        ulonglong2 ap1 = *(const ulonglong2*)&As[k][ty * 8 + 4];  // m-pairs (4,5),(6,7)
        float4 b0 = *(const float4*)&Bs[k][tx * 8];
        float4 b1 = *(const float4*)&Bs[k][tx * 8 + 4];
        unsigned long long ap[4] = {ap0.x, ap0.y, ap1.x, ap1.y};
        unsigned long long bb[8] = {pack_dup_f32x2(b0.x), pack_dup_f32x2(b0.y),
                                    pack_dup_f32x2(b0.z), pack_dup_f32x2(b0.w),
                                    pack_dup_f32x2(b1.x), pack_dup_f32x2(b1.y),
                                    pack_dup_f32x2(b1.z), pack_dup_f32x2(b1.w)};
#pragma unroll
        for (int ip = 0; ip < 4; ip++)
#pragma unroll
            for (int j = 0; j < 8; j++) fma_f32x2(acc2[ip][j], ap[ip], bb[j]);
    }
}

// ============================================================
// GEMM1: pred1[t,R,s] = sum_r transitT[R,r] * (inf[t,r,s]*R0*Rtr[t,r]*Rs[s])
// double-buffered smem pipeline, one __syncthreads per K-tile
__global__ __launch_bounds__(GT) void k_gemm1(const float* __restrict__ inf,
                                              const float* __restrict__ Rtr,
                                              const float* __restrict__ Rs,
                                              const float* __restrict__ R0p) {
    int t  = blockIdx.z;
    int m0 = blockIdx.y * BM;  // R index
    int n0 = blockIdx.x * BN;  // s index
    __shared__ __align__(16) float As[2][BK][BM + 4];
    __shared__ __align__(16) float Bs[2][BK][BN];
    int tid = threadIdx.x;
    int tx = tid & 15, ty = tid >> 4;
    unsigned long long acc2[4][8];
#pragma unroll
    for (int i = 0; i < 4; i++)
#pragma unroll
        for (int j = 0; j < 8; j++) acc2[i][j] = 0ULL;

    const float R0 = *R0p;
    const float* Bt   = inf + (size_t)t * R_ * S_;
    const float* RtrT = Rtr + t * R_;

    // As tile 16x64: lkA in 0..15, lmA in 0..7, m strides by 8 (bijective over 0..63)
    const int lkA = tid & 15, lmA = tid >> 4;
    // Bs tile 16x128: lnB = tid (0..127), each thread loads all 16 k's of its column
    const int lnB = tid;

    float ra[8], rb[BK];
    // ---- load tile 0 ----
#pragma unroll
    for (int i = 0; i < 8; i++) {
        int gm = m0 + lmA + i * 8, gk = lkA;
        As[0][lkA][lmA + i * 8] = (gm < R_ && gk < R_) ? g_transitT[gm * R_ + gk] : 0.f;
    }
    {
        int gn = n0 + lnB;
        float rsn = (gn < S_) ? Rs[gn] : 0.f;
#pragma unroll
        for (int k = 0; k < BK; k++) {
            int gk = k;
            float v = 0.f;
            if (gk < R_ && gn < S_)
                v = Bt[(size_t)gk * S_ + gn] * (R0 * RtrT[gk] * rsn);
            Bs[0][k][lnB] = v;
        }
    }
    __syncthreads();

    const int NT = (R_ + BK - 1) / BK;   // 19
    for (int it = 0; it < NT; it++) {
        int buf = it & 1;
        bool has = (it + 1) < NT;
        if (has) {
            int kb = (it + 1) * BK;
#pragma unroll
            for (int i = 0; i < 8; i++) {
                int gm = m0 + lmA + i * 8, gk = kb + lkA;
                ra[i] = (gm < R_ && gk < R_) ? g_transitT[gm * R_ + gk] : 0.f;
            }
            int gn = n0 + lnB;
            float rsn = (gn < S_) ? Rs[gn] : 0.f;
#pragma unroll
            for (int k = 0; k < BK; k++) {
                int gk = kb + k;
                float v = 0.f;
                if (gk < R_ && gn < S_)
                    v = Bt[(size_t)gk * S_ + gn] * (R0 * RtrT[gk] * rsn);
                rb[k] = v;
            }
        }
        mm_tile(As[buf], Bs[buf], tx, ty, acc2);
        if (has) {
#pragma unroll
            for (int i = 0; i < 8; i++) As[buf ^ 1][lkA][lmA + i * 8] = ra[i];
#pragma unroll
            for (int k = 0; k < BK; k++) Bs[buf ^ 1][k][lnB] = rb[k];
            __syncthreads();
        }
    }

    // store: each thread owns 8 contiguous n's -> 2x STG.128 per m-row.
    // S=500 and gn are multiples of 4 => each float4 is entirely in or out of bounds.
    float* C = g_pred1 + (size_t)t * R_ * S_;
#pragma unroll
    for (int ip = 0; ip < 4; ip++) {
#pragma unroll
        for (int h = 0; h < 2; h++) {
            int gm = m0 + ty * 8 + 2 * ip + h;
            if (gm >= R_) continue;
#pragma unroll
            for (int q = 0; q < 2; q++) {
                int gn = n0 + tx * 8 + q * 4;
                if (gn >= S_) continue;
                float2 f0 = *(float2*)&acc2[ip][q * 4 + 0];
                float2 f1 = *(float2*)&acc2[ip][q * 4 + 1];
                float2 f2 = *(float2*)&acc2[ip][q * 4 + 2];
                float2 f3 = *(float2*)&acc2[ip][q * 4 + 3];
                float4 v = h ? make_float4(f0.y, f1.y, f2.y, f3.y)
                             : make_float4(f0.x, f1.x, f2.x, f3.x);
                *(float4*)&C[(size_t)gm * S_ + gn] = v;
            }
        }
    }
}

// ============================================================
// GEMM2: pred[t,R,S] = sum_s pred1[t,R,s]*mut[s,S]; fused RelaxedPoisson LL epilogue
__global__ __launch_bounds__(GT) void k_gemm2(const float* __restrict__ inf,
                                              const float* __restrict__ iodp,
                                              int slotBase) {
    int t  = blockIdx.z;
    int m0 = blockIdx.y * BM;  // R index
    int n0 = blockIdx.x * BN;  // S index
    __shared__ __align__(16) float As[2][BK][BM + 4];
    __shared__ __align__(16) float Bs[2][BK][BN];
    __shared__ double red[GT];
    int tid = threadIdx.x;
    int tx = tid & 15, ty = tid >> 4;
    unsigned long long acc2[4][8];
#pragma unroll
    for (int i = 0; i < 4; i++)
#pragma unroll
        for (int j = 0; j < 8; j++) acc2[i][j] = 0ULL;

    const float* A = g_pred1 + (size_t)t * R_ * S_;

    const int lkA = tid & 15, lmA = tid >> 4;   // m strides by 8
    const int lnB = tid;                        // Bs: one column, all 16 k's

    float ra[8], rb[BK];
    // ---- load tile 0 ----
#pragma unroll
    for (int i = 0; i < 8; i++) {
        int gm = m0 + lmA + i * 8, gk = lkA;
        As[0][lkA][lmA + i * 8] = (gm < R_ && gk < S_) ? A[(size_t)gm * S_ + gk] : 0.f;
    }
    {
        int gn = n0 + lnB;
#pragma unroll
        for (int k = 0; k < BK; k++)
            Bs[0][k][lnB] = (k < S_ && gn < S_) ? g_mut[k * S_ + gn] : 0.f;
    }
    __syncthreads();

    const int NT = (S_ + BK - 1) / BK;   // 32
    for (int it = 0; it < NT; it++) {
        int buf = it & 1;
        bool has = (it + 1) < NT;
        if (has) {
            int kb = (it + 1) * BK;
#pragma unroll
            for (int i = 0; i < 8; i++) {
                int gm = m0 + lmA + i * 8, gk = kb + lkA;
                ra[i] = (gm < R_ && gk < S_) ? A[(size_t)gm * S_ + gk] : 0.f;
            }
            int gn = n0 + lnB;
#pragma unroll
            for (int k = 0; k < BK; k++) {
                int gk = kb + k;
                rb[k] = (gk < S_ && gn < S_) ? g_mut[gk * S_ + gn] : 0.f;
            }
        }
        mm_tile(As[buf], Bs[buf], tx, ty, acc2);
        if (has) {
#pragma unroll
            for (int i = 0; i < 8; i++) As[buf ^ 1][lkA][lmA + i * 8] = ra[i];
#pragma unroll
            for (int k = 0; k < BK; k++) Bs[buf ^ 1][k][lnB] = rb[k];
            __syncthreads();
        }
    }

    // Epilogue: ll_step terms against infections[t+1]
    const float od = *iodp;
    const float* X = inf + (size_t)(t + 1) * R_ * S_;
    double lsum = 0.0;
#pragma unroll
    for (int ip = 0; ip < 4; ip++) {
#pragma unroll
        for (int j = 0; j < 8; j++) {
            float2 f = *(float2*)&acc2[ip][j];
            int gn = n0 + tx * 8 + j;
            if (gn >= S_) continue;
#pragma unroll
            for (int h = 0; h < 2; h++) {
                int gm = m0 + ty * 8 + 2 * ip + h;
                if (gm >= R_) continue;
                float p  = fmaxf(h ? f.y : f.x, 1e-3f);
                float s2 = log1pf(1.f / p + od);
                float mu = logf(p) - 0.5f * s2;
                float lx = logf(X[(size_t)gm * S_ + gn]);
                float d  = lx - mu;
                lsum += (double)(-lx - 0.5f * logf(s2) - 0.5f * LOG2PI_ - d * d / (2.f * s2));
            }
        }
    }
    red[tid] = lsum;
    __syncthreads();
#pragma unroll
    for (int o = GT / 2; o > 0; o >>= 1) {
        if (tid < o) red[tid] += red[tid + o];
        __syncthreads();
    }
    if (tid == 0) {
        int blin = (blockIdx.z * gridDim.y + blockIdx.y) * gridDim.x + blockIdx.x;
        g_part[slotBase + blin] = red[0];
    }
}

// ============================================================
__device__ __forceinline__ float negbin_lp(float k, float rate, float od) {
    // OverdispersedPoisson -> NB with r = 1/od, q = 1/(1+od*rate)
    float rnb = 1.f / od;
    float lq  = -logf(1.f + od * rate);
    float lp  = logf(od * rate) + lq;   // log(od*rate/(1+od*rate))
    return lgammaf(k + rnb) - lgammaf(rnb) - lgammaf(k + 1.f) + rnb * lq + k * lp;
}

// case + death negbin, Rtr drift. one warp per (t,r)
__global__ void k_misc(const float* __restrict__ inf, const float* __restrict__ crt,
                       const float* __restrict__ crr, const float* __restrict__ Rtr,
                       const float* __restrict__ caseD, const float* __restrict__ deathD,
                       const float* __restrict__ codp, const float* __restrict__ dodp,
                       const float* __restrict__ dsp, int slotBase) {
    __shared__ double red[256];
    int tid  = threadIdx.x;
    int w    = (blockIdx.x * blockDim.x + tid) >> 5;
    int lane = tid & 31;
    double lsum = 0.0;
    if (w < T_ * R_) {
        int t = w / R_, r = w - t * R_;
        const float* row = inf + (size_t)w * S_;
        float ssum = 0.f;
        for (int i = lane; i < S_; i += 32) ssum += row[i];
#pragma unroll
        for (int o = 16; o > 0; o >>= 1) ssum += __shfl_xor_sync(0xffffffffu, ssum, o);
        if (lane == 0) {
            lsum += (double)negbin_lp(caseD[w], ssum * crt[t] * crr[r], *codp);
            lsum += (double)negbin_lp(deathD[w], ssum * DEATH_RATE_, *dodp);
            if (t >= 1) {
                float ds = *dsp;
                float lx = logf(Rtr[w] / Rtr[w - R_]);
                lsum += (double)(-lx - logf(ds) - 0.5f * LOG2PI_ - lx * lx / (2.f * ds * ds));
            }
        }
    }
    red[tid] = lsum;
    __syncthreads();
#pragma unroll
    for (int o = 128; o > 0; o >>= 1) {
        if (tid < o) red[tid] += red[tid + o];
        __syncthreads();
    }
    if (tid == 0) g_part[slotBase + blockIdx.x] = red[0];
}

// ============================================================
__device__ __forceinline__ float blkred_f(float v, float* red, int tid) {
    red[tid] = v;
    __syncthreads();
#pragma unroll
    for (int o = 128; o > 0; o >>= 1) {
        if (tid < o) red[tid] += red[tid + o];
        __syncthreads();
    }
    float r = red[0];
    __syncthreads();
    return r;
}

// strain multinomial; one block per (t, coarse)
__global__ void k_strain(const float* __restrict__ inf, const float* __restrict__ strain,
                         const float* __restrict__ sampleM, int slotBase) {
    __shared__ float w[R_];
    __shared__ float red[256];
    int b = blockIdx.x;
    int t = b / RC_, c = b - t * RC_;
    int tid = threadIdx.x;
    for (int i = tid; i < R_; i += 256) w[i] = sampleM[c * R_ + i];
    __syncthreads();

    int s0 = tid, s1 = tid + 256;
    bool v1 = (s1 < S_);
    float c0 = 1e-6f, c1 = 1e-6f;
    const float* It = inf + (size_t)t * R_ * S_;
    for (int r = 0; r < R_; r++) {
        float wv = w[r];               // uniform across block
        if (wv != 0.f) {
            const float* rowp = It + (size_t)r * S_;
            c0 += wv * rowp[s0];
            if (v1) c1 += wv * rowp[s1];
        }
    }
    float total = blkred_f(c0 + (v1 ? c1 : 0.f), red, tid);

    const float* sd = strain + (size_t)b * S_;
    float sd0 = sd[s0], sd1 = v1 ? sd[s1] : 0.f;
    float lc0 = logf(c0);
    float lc1 = v1 ? logf(c1) : 0.f;

    float slc = blkred_f(sd0 * lc0 + sd1 * lc1, red, tid);
    float slg = blkred_f(lgammaf(sd0 + 1.f) + (v1 ? lgammaf(sd1 + 1.f) : 0.f), red, tid);
    float n   = blkred_f(sd0 + sd1, red, tid);

    if (tid == 0)
        g_part[slotBase + b] = (double)(lgammaf(n + 1.f) - slg + slc - n * logf(total));
}

// ============================================================
__global__ void k_final(float* __restrict__ out) {
    __shared__ double red[256];
    int tid = threadIdx.x;
    double s = 0.0;
    for (int i = tid; i < NSLOTS; i += 256) s += g_part[i];   // fixed order: deterministic
    red[tid] = s;
    __syncthreads();
#pragma unroll
    for (int o = 128; o > 0; o >>= 1) {
        if (tid < o) red[tid] += red[tid + o];
        __syncthreads();
    }
    if (tid == 0) out[0] = (float)red[0];
}

// ============================================================
extern "C" void kernel_launch(void* const* d_in, const int* in_sizes, int n_in,
                              void* d_out, int out_size) {
    const float* inf    = (const float*)d_in[0];
    const float* crt    = (const float*)d_in[1];
    const float* crr    = (const float*)d_in[2];
    const float* R0p    = (const float*)d_in[3];
    const float* Rs     = (const float*)d_in[4];
    const float* Rtr    = (const float*)d_in[5];
    const float* trate  = (const float*)d_in[6];
    const float* mrp    = (const float*)d_in[7];
    const float* iodp   = (const float*)d_in[8];
    const float* codp   = (const float*)d_in[9];
    const float* dodp   = (const float*)d_in[10];
    const float* dsp    = (const float*)d_in[11];
    const float* td     = (const float*)d_in[12];
    const float* caseD  = (const float*)d_in[13];
    const float* deathD = (const float*)d_in[14];
    const float* strain = (const float*)d_in[15];
    const float* sampM  = (const float*)d_in[16];
    const float* mm     = (const float*)d_in[17];
    float* out = (float*)d_out;

    k_init<<<(NSLOTS + 255) / 256, 256>>>();
    k_prep<<<(S_ * S_ + 255) / 256, 256>>>(td, trate, mm, mrp);

    dim3 gg((S_ + BN - 1) / BN, (R_ + BM - 1) / BM, T_ - 1);   // (4, 5, 99)
    k_gemm1<<<gg, GT>>>(inf, Rtr, Rs, R0p);
    k_gemm2<<<gg, GT>>>(inf, iodp, SLOT_GEMM2);

    k_misc<<<(T_ * R_ * 32 + 255) / 256, 256>>>(inf, crt, crr, Rtr, caseD, deathD,
                                                codp, dodp, dsp, SLOT_MISC);
    k_strain<<<T_ * RC_, 256>>>(inf, strain, sampM, SLOT_STRAIN);
    k_final<<<1, 256>>>(out);
}

// round 11
// speedup vs baseline: 1.1975x; 1.1975x over previous
#include <cuda_runtime.h>

#define T_   100
#define R_   300
#define S_   500
#define P_   8
#define RC_  50
#define LOG2PI_ 1.8378770664093453f
#define DEATH_RATE_ 0.02f

#define BM 64
#define BN 128
#define BK 16
#define GT 128   // threads per GEMM block; micro tile 8x8 (m-pairs packed f32x2)

#define NSLOTS 16384
#define SLOT_GEMM2  0      // 1980 blocks
#define SLOT_MISC   4096   // 3750 blocks
#define SLOT_STRAIN 8192   // 5000 blocks

// ---- scratch (device globals; no allocation allowed) ----
__device__ float  g_transitT[R_ * R_];                    // transitT[R][r] = transit[r][R]
__device__ float  g_mut[S_ * S_];                         // mut[s][S]
__device__ float  g_pred1[(size_t)(T_ - 1) * R_ * S_];    // 59.4 MB
__device__ double g_part[NSLOTS];

// packed f32x2 helpers (sm_103a) -------------------------------------------
__device__ __forceinline__ unsigned long long pack_dup_f32x2(float v) {
    unsigned long long d;
    unsigned int u = __float_as_uint(v);
    asm("mov.b64 %0, {%1, %1};" : "=l"(d) : "r"(u));
    return d;
}
__device__ __forceinline__ void fma_f32x2(unsigned long long& acc,
                                          unsigned long long a,
                                          unsigned long long b) {
    asm("fma.rn.f32x2 %0, %1, %2, %0;" : "+l"(acc) : "l"(a), "l"(b));
}

// cp.async helpers ----------------------------------------------------------
__device__ __forceinline__ void cp_async16(void* smem_dst, const void* gsrc, int src_bytes) {
    unsigned int saddr = (unsigned int)__cvta_generic_to_shared(smem_dst);
    asm volatile("cp.async.cg.shared.global [%0], [%1], 16, %2;"
                 :: "r"(saddr), "l"(gsrc), "r"(src_bytes));
}
#define CP_COMMIT() asm volatile("cp.async.commit_group;" ::: "memory")
#define CP_WAIT0()  asm volatile("cp.async.wait_group 0;" ::: "memory")

// ============================================================
__global__ void k_init() {
    int i = blockIdx.x * blockDim.x + threadIdx.x;
    if (i < NSLOTS) g_part[i] = 0.0;
}

__global__ void k_prep(const float* __restrict__ td, const float* __restrict__ tr,
                       const float* __restrict__ mm, const float* __restrict__ mrp) {
    int i = blockIdx.x * blockDim.x + threadIdx.x;
    if (i < R_ * R_) {
        int Rr = i / R_, r = i - Rr * R_;
        float a = 0.f;
#pragma unroll
        for (int p = 0; p < P_; p++)
            a += td[((size_t)r * R_ + Rr) * P_ + p] * tr[p];
        g_transitT[i] = a;   // = transit[r][Rr]
    }
    if (i < S_ * S_) {
        int s = i / S_, sn = i - s * S_;
        g_mut[i] = (s == sn ? 1.f : 0.f) + (*mrp) * mm[i];
    }
}

// ============================================================
// Compute step on one smem tile: 8(m) x 8(n) micro-tile, m-pairs packed f32x2.
__device__ __forceinline__ void mm_tile(const float (*As)[BM + 4], const float (*Bs)[BN],
                                        int tx, int ty, unsigned long long acc2[4][8]) {
#pragma unroll
    for (int k = 0; k < BK; k++) {
        ulonglong2 ap0 = *(const ulonglong2*)&As[k][ty * 8];      // m-pairs (0,1),(2,3)
        ulonglong2 ap1 = *(const ulonglong2*)&As[k][ty * 8 + 4];  // m-pairs (4,5),(6,7)
        float4 b0 = *(const float4*)&Bs[k][tx * 8];
        float4 b1 = *(const float4*)&Bs[k][tx * 8 + 4];
        unsigned long long ap[4] = {ap0.x, ap0.y, ap1.x, ap1.y};
        unsigned long long bb[8] = {pack_dup_f32x2(b0.x), pack_dup_f32x2(b0.y),
                                    pack_dup_f32x2(b0.z), pack_dup_f32x2(b0.w),
                                    pack_dup_f32x2(b1.x), pack_dup_f32x2(b1.y),
                                    pack_dup_f32x2(b1.z), pack_dup_f32x2(b1.w)};
#pragma unroll
        for (int ip = 0; ip < 4; ip++)
#pragma unroll
            for (int j = 0; j < 8; j++) fma_f32x2(acc2[ip][j], ap[ip], bb[j]);
    }
}

// B-tile async copy: 16 x 128 floats = 512 x 16B chunks, 4 per thread.
// rowLimit = valid k bound (exclusive, global); base = row-major src with ld elements.
__device__ __forceinline__ void b_tile_cp(float (*dst)[BN], const float* __restrict__ base,
                                          int ld, int kb, int rowLimit, int n0, int tid) {
#pragma unroll
    for (int i = 0; i < 4; i++) {
        int chunk = i * GT + tid;            // 0..511
        int kk = chunk >> 5;                 // 0..15
        int cc = (chunk & 31) * 4;           // 0,4,...,124
        int gk = kb + kk, gn = n0 + cc;
        bool ok = (gk < rowLimit) && (gn + 3 < S_);
        cp_async16(&dst[kk][cc], ok ? &base[(size_t)gk * ld + gn] : base, ok ? 16 : 0);
    }
}

// ============================================================
// GEMM1: pred1[t,R,s] = [sum_r (transitT[R,r]*Rtr[t,r]) * inf[t,r,s]] * (R0*Rs[s])
// B tile (inf) is a raw copy -> cp.async; Rtr folded into A; R0*Rs applied at store.
__global__ __launch_bounds__(GT, 4) void k_gemm1(const float* __restrict__ inf,
                                                 const float* __restrict__ Rtr,
                                                 const float* __restrict__ Rs,
                                                 const float* __restrict__ R0p) {
    int t  = blockIdx.z;
    int m0 = blockIdx.y * BM;  // R index
    int n0 = blockIdx.x * BN;  // s index
    __shared__ __align__(16) float As[2][BK][BM + 4];
    __shared__ __align__(16) float Bs[2][BK][BN];
    int tid = threadIdx.x;
    int tx = tid & 15, ty = tid >> 4;
    unsigned long long acc2[4][8];
#pragma unroll
    for (int i = 0; i < 4; i++)
#pragma unroll
        for (int j = 0; j < 8; j++) acc2[i][j] = 0ULL;

    const float* Bt   = inf + (size_t)t * R_ * S_;
    const float* RtrT = Rtr + t * R_;

    // As tile 16x64: lkA in 0..15, lmA in 0..7, m strides by 8 (bijective over 0..63)
    const int lkA = tid & 15, lmA = tid >> 4;

    float ra[8];
    // ---- tile 0: B via cp.async, A via registers ----
    b_tile_cp(Bs[0], Bt, S_, 0, R_, n0, tid);
    CP_COMMIT();
    {
        float rt = (lkA < R_) ? RtrT[lkA] : 0.f;
#pragma unroll
        for (int i = 0; i < 8; i++) {
            int gm = m0 + lmA + i * 8;
            As[0][lkA][lmA + i * 8] = (gm < R_ && lkA < R_) ? g_transitT[gm * R_ + lkA] * rt : 0.f;
        }
    }
    CP_WAIT0();
    __syncthreads();

    const int NT = (R_ + BK - 1) / BK;   // 19
    for (int it = 0; it < NT; it++) {
        int buf = it & 1;
        bool has = (it + 1) < NT;
        if (has) {
            int kb = (it + 1) * BK;
            b_tile_cp(Bs[buf ^ 1], Bt, S_, kb, R_, n0, tid);
            CP_COMMIT();
            int gk = kb + lkA;
            float rt = (gk < R_) ? RtrT[gk] : 0.f;
#pragma unroll
            for (int i = 0; i < 8; i++) {
                int gm = m0 + lmA + i * 8;
                ra[i] = (gm < R_ && gk < R_) ? g_transitT[gm * R_ + gk] * rt : 0.f;
            }
        }
        mm_tile(As[buf], Bs[buf], tx, ty, acc2);
        if (has) {
#pragma unroll
            for (int i = 0; i < 8; i++) As[buf ^ 1][lkA][lmA + i * 8] = ra[i];
            CP_WAIT0();
            __syncthreads();
        }
    }

    // store with R0*Rs[gn] scaling: 2x STG.128 per m-row.
    // S=500, gn multiples of 4 => each float4 entirely in or out of bounds.
    const float R0 = *R0p;
    float* C = g_pred1 + (size_t)t * R_ * S_;
    int gnb = n0 + tx * 8;
    float4 rs[2];
#pragma unroll
    for (int q = 0; q < 2; q++)
        rs[q] = (gnb + q * 4 < S_) ? *(const float4*)&Rs[gnb + q * 4]
                                   : make_float4(0.f, 0.f, 0.f, 0.f);
#pragma unroll
    for (int ip = 0; ip < 4; ip++) {
#pragma unroll
        for (int h = 0; h < 2; h++) {
            int gm = m0 + ty * 8 + 2 * ip + h;
            if (gm >= R_) continue;
#pragma unroll
            for (int q = 0; q < 2; q++) {
                int gn = gnb + q * 4;
                if (gn >= S_) continue;
                float2 f0 = *(float2*)&acc2[ip][q * 4 + 0];
                float2 f1 = *(float2*)&acc2[ip][q * 4 + 1];
                float2 f2 = *(float2*)&acc2[ip][q * 4 + 2];
                float2 f3 = *(float2*)&acc2[ip][q * 4 + 3];
                float4 v = h ? make_float4(f0.y, f1.y, f2.y, f3.y)
                             : make_float4(f0.x, f1.x, f2.x, f3.x);
                v.x *= R0 * rs[q].x; v.y *= R0 * rs[q].y;
                v.z *= R0 * rs[q].z; v.w *= R0 * rs[q].w;
                *(float4*)&C[(size_t)gm * S_ + gn] = v;
            }
        }
    }
}

// ============================================================
// GEMM2: pred[t,R,S] = sum_s pred1[t,R,s]*mut[s,S]; fused RelaxedPoisson LL epilogue
__global__ __launch_bounds__(GT, 4) void k_gemm2(const float* __restrict__ inf,
                                                 const float* __restrict__ iodp,
                                                 int slotBase) {
    int t  = blockIdx.z;
    int m0 = blockIdx.y * BM;  // R index
    int n0 = blockIdx.x * BN;  // S index
    __shared__ __align__(16) float As[2][BK][BM + 4];
    __shared__ __align__(16) float Bs[2][BK][BN];
    __shared__ double red[GT];
    int tid = threadIdx.x;
    int tx = tid & 15, ty = tid >> 4;
    unsigned long long acc2[4][8];
#pragma unroll
    for (int i = 0; i < 4; i++)
#pragma unroll
        for (int j = 0; j < 8; j++) acc2[i][j] = 0ULL;

    const float* A = g_pred1 + (size_t)t * R_ * S_;

    const int lkA = tid & 15, lmA = tid >> 4;   // m strides by 8

    float ra[8];
    // ---- tile 0 ----
    b_tile_cp(Bs[0], g_mut, S_, 0, S_, n0, tid);
    CP_COMMIT();
#pragma unroll
    for (int i = 0; i < 8; i++) {
        int gm = m0 + lmA + i * 8;
        As[0][lkA][lmA + i * 8] = (gm < R_ && lkA < S_) ? A[(size_t)gm * S_ + lkA] : 0.f;
    }
    CP_WAIT0();
    __syncthreads();

    const int NT = (S_ + BK - 1) / BK;   // 32
    for (int it = 0; it < NT; it++) {
        int buf = it & 1;
        bool has = (it + 1) < NT;
        if (has) {
            int kb = (it + 1) * BK;
            b_tile_cp(Bs[buf ^ 1], g_mut, S_, kb, S_, n0, tid);
            CP_COMMIT();
            int gk = kb + lkA;
#pragma unroll
            for (int i = 0; i < 8; i++) {
                int gm = m0 + lmA + i * 8;
                ra[i] = (gm < R_ && gk < S_) ? A[(size_t)gm * S_ + gk] : 0.f;
            }
        }
        mm_tile(As[buf], Bs[buf], tx, ty, acc2);
        if (has) {
#pragma unroll
            for (int i = 0; i < 8; i++) As[buf ^ 1][lkA][lmA + i * 8] = ra[i];
            CP_WAIT0();
            __syncthreads();
        }
    }

    // Epilogue: ll_step terms against infections[t+1]
    const float od = *iodp;
    const float* X = inf + (size_t)(t + 1) * R_ * S_;
    double lsum = 0.0;
#pragma unroll
    for (int ip = 0; ip < 4; ip++) {
#pragma unroll
        for (int j = 0; j < 8; j++) {
            float2 f = *(float2*)&acc2[ip][j];
            int gn = n0 + tx * 8 + j;
            if (gn >= S_) continue;
#pragma unroll
            for (int h = 0; h < 2; h++) {
                int gm = m0 + ty * 8 + 2 * ip + h;
                if (gm >= R_) continue;
                float p  = fmaxf(h ? f.y : f.x, 1e-3f);
                float s2 = log1pf(1.f / p + od);
                float mu = logf(p) - 0.5f * s2;
                float lx = logf(X[(size_t)gm * S_ + gn]);
                float d  = lx - mu;
                lsum += (double)(-lx - 0.5f * logf(s2) - 0.5f * LOG2PI_ - d * d / (2.f * s2));
            }
        }
    }
    red[tid] = lsum;
    __syncthreads();
#pragma unroll
    for (int o = GT / 2; o > 0; o >>= 1) {
        if (tid < o) red[tid] += red[tid + o];
        __syncthreads();
    }
    if (tid == 0) {
        int blin = (blockIdx.z * gridDim.y + blockIdx.y) * gridDim.x + blockIdx.x;
        g_part[slotBase + blin] = red[0];
    }
}

// ============================================================
__device__ __forceinline__ float negbin_lp(float k, float rate, float od) {
    // OverdispersedPoisson -> NB with r = 1/od, q = 1/(1+od*rate)
    float rnb = 1.f / od;
    float lq  = -logf(1.f + od * rate);
    float lp  = logf(od * rate) + lq;   // log(od*rate/(1+od*rate))
    return lgammaf(k + rnb) - lgammaf(rnb) - lgammaf(k + 1.f) + rnb * lq + k * lp;
}

// case + death negbin, Rtr drift. one warp per (t,r)
__global__ void k_misc(const float* __restrict__ inf, const float* __restrict__ crt,
                       const float* __restrict__ crr, const float* __restrict__ Rtr,
                       const float* __restrict__ caseD, const float* __restrict__ deathD,
                       const float* __restrict__ codp, const float* __restrict__ dodp,
                       const float* __restrict__ dsp, int slotBase) {
    __shared__ double red[256];
    int tid  = threadIdx.x;
    int w    = (blockIdx.x * blockDim.x + tid) >> 5;
    int lane = tid & 31;
    double lsum = 0.0;
    if (w < T_ * R_) {
        int t = w / R_, r = w - t * R_;
        const float* row = inf + (size_t)w * S_;
        float ssum = 0.f;
        for (int i = lane; i < S_; i += 32) ssum += row[i];
#pragma unroll
        for (int o = 16; o > 0; o >>= 1) ssum += __shfl_xor_sync(0xffffffffu, ssum, o);
        if (lane == 0) {
            lsum += (double)negbin_lp(caseD[w], ssum * crt[t] * crr[r], *codp);
            lsum += (double)negbin_lp(deathD[w], ssum * DEATH_RATE_, *dodp);
            if (t >= 1) {
                float ds = *dsp;
                float lx = logf(Rtr[w] / Rtr[w - R_]);
                lsum += (double)(-lx - logf(ds) - 0.5f * LOG2PI_ - lx * lx / (2.f * ds * ds));
            }
        }
    }
    red[tid] = lsum;
    __syncthreads();
#pragma unroll
    for (int o = 128; o > 0; o >>= 1) {
        if (tid < o) red[tid] += red[tid + o];
        __syncthreads();
    }
    if (tid == 0) g_part[slotBase + blockIdx.x] = red[0];
}

// ============================================================
__device__ __forceinline__ float blkred_f(float v, float* red, int tid) {
    red[tid] = v;
    __syncthreads();
#pragma unroll
    for (int o = 128; o > 0; o >>= 1) {
        if (tid < o) red[tid] += red[tid + o];
        __syncthreads();
    }
    float r = red[0];
    __syncthreads();
    return r;
}

// strain multinomial; one block per (t, coarse)
__global__ void k_strain(const float* __restrict__ inf, const float* __restrict__ strain,
                         const float* __restrict__ sampleM, int slotBase) {
    __shared__ float w[R_];
    __shared__ float red[256];
    int b = blockIdx.x;
    int t = b / RC_, c = b - t * RC_;
    int tid = threadIdx.x;
    for (int i = tid; i < R_; i += 256) w[i] = sampleM[c * R_ + i];
    __syncthreads();

    int s0 = tid, s1 = tid + 256;
    bool v1 = (s1 < S_);
    float c0 = 1e-6f, c1 = 1e-6f;
    const float* It = inf + (size_t)t * R_ * S_;
    for (int r = 0; r < R_; r++) {
        float wv = w[r];               // uniform across block
        if (wv != 0.f) {
            const float* rowp = It + (size_t)r * S_;
            c0 += wv * rowp[s0];
            if (v1) c1 += wv * rowp[s1];
        }
    }
    float total = blkred_f(c0 + (v1 ? c1 : 0.f), red, tid);

    const float* sd = strain + (size_t)b * S_;
    float sd0 = sd[s0], sd1 = v1 ? sd[s1] : 0.f;
    float lc0 = logf(c0);
    float lc1 = v1 ? logf(c1) : 0.f;

    float slc = blkred_f(sd0 * lc0 + sd1 * lc1, red, tid);
    float slg = blkred_f(lgammaf(sd0 + 1.f) + (v1 ? lgammaf(sd1 + 1.f) : 0.f), red, tid);
    float n   = blkred_f(sd0 + sd1, red, tid);

    if (tid == 0)
        g_part[slotBase + b] = (double)(lgammaf(n + 1.f) - slg + slc - n * logf(total));
}

// ============================================================
__global__ void k_final(float* __restrict__ out) {
    __shared__ double red[256];
    int tid = threadIdx.x;
    double s = 0.0;
    for (int i = tid; i < NSLOTS; i += 256) s += g_part[i];   // fixed order: deterministic
    red[tid] = s;
    __syncthreads();
#pragma unroll
    for (int o = 128; o > 0; o >>= 1) {
        if (tid < o) red[tid] += red[tid + o];
        __syncthreads();
    }
    if (tid == 0) out[0] = (float)red[0];
}

// ============================================================
extern "C" void kernel_launch(void* const* d_in, const int* in_sizes, int n_in,
                              void* d_out, int out_size) {
    const float* inf    = (const float*)d_in[0];
    const float* crt    = (const float*)d_in[1];
    const float* crr    = (const float*)d_in[2];
    const float* R0p    = (const float*)d_in[3];
    const float* Rs     = (const float*)d_in[4];
    const float* Rtr    = (const float*)d_in[5];
    const float* trate  = (const float*)d_in[6];
    const float* mrp    = (const float*)d_in[7];
    const float* iodp   = (const float*)d_in[8];
    const float* codp   = (const float*)d_in[9];
    const float* dodp   = (const float*)d_in[10];
    const float* dsp    = (const float*)d_in[11];
    const float* td     = (const float*)d_in[12];
    const float* caseD  = (const float*)d_in[13];
    const float* deathD = (const float*)d_in[14];
    const float* strain = (const float*)d_in[15];
    const float* sampM  = (const float*)d_in[16];
    const float* mm     = (const float*)d_in[17];
    float* out = (float*)d_out;

    k_init<<<(NSLOTS + 255) / 256, 256>>>();
    k_prep<<<(S_ * S_ + 255) / 256, 256>>>(td, trate, mm, mrp);

    dim3 gg((S_ + BN - 1) / BN, (R_ + BM - 1) / BM, T_ - 1);   // (4, 5, 99)
    k_gemm1<<<gg, GT>>>(inf, Rtr, Rs, R0p);
    k_gemm2<<<gg, GT>>>(inf, iodp, SLOT_GEMM2);

    k_misc<<<(T_ * R_ * 32 + 255) / 256, 256>>>(inf, crt, crr, Rtr, caseD, deathD,
                                                codp, dodp, dsp, SLOT_MISC);
    k_strain<<<T_ * RC_, 256>>>(inf, strain, sampM, SLOT_STRAIN);
    k_final<<<1, 256>>>(out);
}

// round 15
// speedup vs baseline: 1.3677x; 1.1421x over previous
#include <cuda_runtime.h>
#include <cuda_bf16.h>
#include <cstdint>

#define T_   100
#define R_   300
#define S_   500
#define P_   8
#define RC_  50
#define LOG2PI_ 1.8378770664093453f
#define DEATH_RATE_ 0.02f

#define MPAD 384     // padded R for MMA m-tiles (3 x 128)
#define KPAD 512     // padded S/K stride (bf16 rows 1024B)

// ---- gemm1 (SIMT) tiling ----
#define BM 64
#define BN 128
#define BK 16
#define GT 128

#define NSLOTS 16384
#define SLOT_GEMM2  0      // 1188 blocks
#define SLOT_MISC   4096   // 3750 blocks
#define SLOT_STRAIN 8192   // 5000 blocks

// ---- scratch (device globals; zero-initialized at load; no allocation) ----
__device__ float          g_transitT[R_ * R_];                         // transitT[R][r]
__device__ __nv_bfloat16  g_pred1b[(size_t)(T_ - 1) * MPAD * KPAD];    // 39MB, pads stay 0
__device__ __nv_bfloat16  g_mutB[KPAD * KPAD];                         // B[n][k] = mut[k][n]
__device__ double         g_part[NSLOTS];

// ===================== ptx helpers =====================
__device__ __forceinline__ unsigned long long pack_dup_f32x2(float v) {
    unsigned long long d; unsigned int u = __float_as_uint(v);
    asm("mov.b64 %0, {%1, %1};" : "=l"(d) : "r"(u)); return d;
}
__device__ __forceinline__ void fma_f32x2(unsigned long long& acc,
                                          unsigned long long a, unsigned long long b) {
    asm("fma.rn.f32x2 %0, %1, %2, %0;" : "+l"(acc) : "l"(a), "l"(b));
}
__device__ __forceinline__ void cp_async16(void* smem_dst, const void* gsrc, int src_bytes) {
    unsigned int saddr = (unsigned int)__cvta_generic_to_shared(smem_dst);
    asm volatile("cp.async.cg.shared.global [%0], [%1], 16, %2;"
                 :: "r"(saddr), "l"(gsrc), "r"(src_bytes));
}
#define CP_COMMIT() asm volatile("cp.async.commit_group;" ::: "memory")
#define CP_WAIT0()  asm volatile("cp.async.wait_group 0;" ::: "memory")

// mma.sync m16n8k16 row.col f32 += bf16*bf16 (sm_80+, valid on plain sm_103 target)
__device__ __forceinline__ void mma16816(float* d, const uint32_t* a, const uint32_t* b) {
    asm volatile("mma.sync.aligned.m16n8k16.row.col.f32.bf16.bf16.f32 "
                 "{%0,%1,%2,%3}, {%4,%5,%6,%7}, {%8,%9}, {%0,%1,%2,%3};"
                 : "+f"(d[0]), "+f"(d[1]), "+f"(d[2]), "+f"(d[3])
                 : "r"(a[0]), "r"(a[1]), "r"(a[2]), "r"(a[3]), "r"(b[0]), "r"(b[1]));
}

// ============================================================
__global__ void k_init() {
    int i = blockIdx.x * blockDim.x + threadIdx.x;
    if (i < NSLOTS) g_part[i] = 0.0;
}

__global__ void k_prep(const float* __restrict__ td, const float* __restrict__ tr,
                       const float* __restrict__ mm, const float* __restrict__ mrp) {
    int i = blockIdx.x * blockDim.x + threadIdx.x;
    if (i < R_ * R_) {
        int Rr = i / R_, r = i - Rr * R_;
        float a = 0.f;
#pragma unroll
        for (int p = 0; p < P_; p++)
            a += td[((size_t)r * R_ + Rr) * P_ + p] * tr[p];
        g_transitT[i] = a;
    }
    if (i < KPAD * KPAD) {    // B[n][k] = mut[k][n], bf16, zero-padded
        int n = i >> 9, k = i & 511;
        float v = 0.f;
        if (n < S_ && k < S_)
            v = (k == n ? 1.f : 0.f) + (*mrp) * mm[k * S_ + n];
        g_mutB[i] = __float2bfloat16(v);
    }
}

// ============================================================
// GEMM1 (SIMT f32x2): pred1[t,m,s] = [sum_r transitT[m,r]*Rtr[t,r]*inf[t,r,s]] * R0*Rs[s]
// Output: bf16 into g_pred1b with KPAD stride; pad cols 500..511 written as 0.
__device__ __forceinline__ void mm_tile(const float (*As)[BM + 4], const float (*Bs)[BN],
                                        int tx, int ty, unsigned long long acc2[4][8]) {
#pragma unroll
    for (int k = 0; k < BK; k++) {
        ulonglong2 ap0 = *(const ulonglong2*)&As[k][ty * 8];
        ulonglong2 ap1 = *(const ulonglong2*)&As[k][ty * 8 + 4];
        float4 b0 = *(const float4*)&Bs[k][tx * 8];
        float4 b1 = *(const float4*)&Bs[k][tx * 8 + 4];
        unsigned long long ap[4] = {ap0.x, ap0.y, ap1.x, ap1.y};
        unsigned long long bb[8] = {pack_dup_f32x2(b0.x), pack_dup_f32x2(b0.y),
                                    pack_dup_f32x2(b0.z), pack_dup_f32x2(b0.w),
                                    pack_dup_f32x2(b1.x), pack_dup_f32x2(b1.y),
                                    pack_dup_f32x2(b1.z), pack_dup_f32x2(b1.w)};
#pragma unroll
        for (int ip = 0; ip < 4; ip++)
#pragma unroll
            for (int j = 0; j < 8; j++) fma_f32x2(acc2[ip][j], ap[ip], bb[j]);
    }
}

__device__ __forceinline__ void b_tile_cp(float (*dst)[BN], const float* __restrict__ base,
                                          int ld, int kb, int rowLimit, int n0, int tid) {
#pragma unroll
    for (int i = 0; i < 4; i++) {
        int chunk = i * GT + tid;
        int kk = chunk >> 5;
        int cc = (chunk & 31) * 4;
        int gk = kb + kk, gn = n0 + cc;
        bool ok = (gk < rowLimit) && (gn + 3 < S_);
        cp_async16(&dst[kk][cc], ok ? &base[(size_t)gk * ld + gn] : base, ok ? 16 : 0);
    }
}

__global__ __launch_bounds__(GT, 4) void k_gemm1(const float* __restrict__ inf,
                                                 const float* __restrict__ Rtr,
                                                 const float* __restrict__ Rs,
                                                 const float* __restrict__ R0p) {
    int t  = blockIdx.z;
    int m0 = blockIdx.y * BM;
    int n0 = blockIdx.x * BN;
    __shared__ __align__(16) float As[2][BK][BM + 4];
    __shared__ __align__(16) float Bs[2][BK][BN];
    int tid = threadIdx.x;
    int tx = tid & 15, ty = tid >> 4;
    unsigned long long acc2[4][8];
#pragma unroll
    for (int i = 0; i < 4; i++)
#pragma unroll
        for (int j = 0; j < 8; j++) acc2[i][j] = 0ULL;

    const float* Bt   = inf + (size_t)t * R_ * S_;
    const float* RtrT = Rtr + t * R_;
    const int lkA = tid & 15, lmA = tid >> 4;   // m strides by 8

    float ra[8];
    b_tile_cp(Bs[0], Bt, S_, 0, R_, n0, tid);
    CP_COMMIT();
    {
        float rt = (lkA < R_) ? RtrT[lkA] : 0.f;
#pragma unroll
        for (int i = 0; i < 8; i++) {
            int gm = m0 + lmA + i * 8;
            As[0][lkA][lmA + i * 8] = (gm < R_ && lkA < R_) ? g_transitT[gm * R_ + lkA] * rt : 0.f;
        }
    }
    CP_WAIT0();
    __syncthreads();

    const int NT = (R_ + BK - 1) / BK;   // 19
    for (int it = 0; it < NT; it++) {
        int buf = it & 1;
        bool has = (it + 1) < NT;
        if (has) {
            int kb = (it + 1) * BK;
            b_tile_cp(Bs[buf ^ 1], Bt, S_, kb, R_, n0, tid);
            CP_COMMIT();
            int gk = kb + lkA;
            float rt = (gk < R_) ? RtrT[gk] : 0.f;
#pragma unroll
            for (int i = 0; i < 8; i++) {
                int gm = m0 + lmA + i * 8;
                ra[i] = (gm < R_ && gk < R_) ? g_transitT[gm * R_ + gk] * rt : 0.f;
            }
        }
        mm_tile(As[buf], Bs[buf], tx, ty, acc2);
        if (has) {
#pragma unroll
            for (int i = 0; i < 8; i++) As[buf ^ 1][lkA][lmA + i * 8] = ra[i];
            CP_WAIT0();
            __syncthreads();
        }
    }

    // bf16 store, scaled by R0*Rs[n]; pad cols (>=500) get 0 (rs=0, acc=0)
    const float R0 = *R0p;
    __nv_bfloat16* C = g_pred1b + (size_t)t * MPAD * KPAD;
    int gnb = n0 + tx * 8;
    float4 rs[2];
#pragma unroll
    for (int q = 0; q < 2; q++)
        rs[q] = (gnb + q * 4 < S_) ? *(const float4*)&Rs[gnb + q * 4]
                                   : make_float4(0.f, 0.f, 0.f, 0.f);
#pragma unroll
    for (int ip = 0; ip < 4; ip++) {
#pragma unroll
        for (int h = 0; h < 2; h++) {
            int gm = m0 + ty * 8 + 2 * ip + h;
            if (gm >= R_) continue;
            __nv_bfloat16* Crow = C + (size_t)gm * KPAD;
#pragma unroll
            for (int q = 0; q < 2; q++) {
                int gn = gnb + q * 4;      // < 512 always
                float2 f0 = *(float2*)&acc2[ip][q * 4 + 0];
                float2 f1 = *(float2*)&acc2[ip][q * 4 + 1];
                float2 f2 = *(float2*)&acc2[ip][q * 4 + 2];
                float2 f3 = *(float2*)&acc2[ip][q * 4 + 3];
                float4 v = h ? make_float4(f0.y, f1.y, f2.y, f3.y)
                             : make_float4(f0.x, f1.x, f2.x, f3.x);
                v.x *= R0 * rs[q].x; v.y *= R0 * rs[q].y;
                v.z *= R0 * rs[q].z; v.w *= R0 * rs[q].w;
                __nv_bfloat162 b01 = __floats2bfloat162_rn(v.x, v.y);
                __nv_bfloat162 b23 = __floats2bfloat162_rn(v.z, v.w);
                uint2 pk;
                pk.x = *(unsigned int*)&b01;
                pk.y = *(unsigned int*)&b23;
                *(uint2*)(Crow + gn) = pk;   // 8B-aligned (gn%4==0, row 1024B)
            }
        }
    }
}

// ============================================================
// GEMM2 via mma.sync (HMMA bf16, fp32 accum): D[128,128] per block.
// A = g_pred1b (row-major, k contiguous), B = g_mutB (col-major B: B[k][n] with
// k contiguous per n-row). Warp tile 32(m) x 64(n) = 2 x 8 fragments, K = 512.
// Fused RelaxedPoisson LL epilogue straight from accumulator registers.
__global__ __launch_bounds__(256, 2) void k_gemm2m(const float* __restrict__ inf,
                                                   const float* __restrict__ iodp,
                                                   int slotBase) {
    const int t  = blockIdx.z;
    const int m0 = blockIdx.y * 128;
    const int n0 = blockIdx.x * 128;
    const int tid = threadIdx.x, wid = tid >> 5, lane = tid & 31;
    const int wm = (wid & 3) * 32;     // warp m offset in tile
    const int wn = (wid >> 2) * 64;    // warp n offset in tile
    const int gid = lane >> 2, qid = lane & 3;

    const __nv_bfloat16* A = g_pred1b + (size_t)t * MPAD * KPAD;
    const __nv_bfloat16* arow = A + (size_t)(m0 + wm + gid) * KPAD + qid * 2;
    const __nv_bfloat16* brow = g_mutB + (size_t)(n0 + wn + gid) * KPAD + qid * 2;

    float acc[2][8][4];
#pragma unroll
    for (int i = 0; i < 2; i++)
#pragma unroll
        for (int j = 0; j < 8; j++)
#pragma unroll
            for (int c = 0; c < 4; c++) acc[i][j][c] = 0.f;

    for (int kk = 0; kk < KPAD; kk += 16) {
        uint32_t a[2][4], b[8][2];
#pragma unroll
        for (int i = 0; i < 2; i++) {
            const __nv_bfloat16* p = arow + (size_t)i * 16 * KPAD + kk;
            a[i][0] = *(const uint32_t*)(p);
            a[i][1] = *(const uint32_t*)(p + 8 * KPAD);
            a[i][2] = *(const uint32_t*)(p + 8);
            a[i][3] = *(const uint32_t*)(p + 8 * KPAD + 8);
        }
#pragma unroll
        for (int j = 0; j < 8; j++) {
            const __nv_bfloat16* p = brow + (size_t)j * 8 * KPAD + kk;
            b[j][0] = *(const uint32_t*)(p);
            b[j][1] = *(const uint32_t*)(p + 8);
        }
#pragma unroll
        for (int i = 0; i < 2; i++)
#pragma unroll
            for (int j = 0; j < 8; j++) mma16816(acc[i][j], a[i], b[j]);
    }

    // Epilogue: lane owns rows m0+wm+i*16+gid(+8), cols n0+wn+j*8+qid*2(+1)
    const float od = *iodp;
    const float* X = inf + (size_t)(t + 1) * R_ * S_;
    double lsum = 0.0;
#pragma unroll
    for (int i = 0; i < 2; i++) {
#pragma unroll
        for (int h = 0; h < 2; h++) {
            int gm = m0 + wm + i * 16 + gid + h * 8;
            if (gm >= R_) continue;
            const float* Xr = X + (size_t)gm * S_;
#pragma unroll
            for (int j = 0; j < 8; j++) {
                int col0 = n0 + wn + j * 8 + qid * 2;
#pragma unroll
                for (int e = 0; e < 2; e++) {
                    int gn = col0 + e;
                    if (gn >= S_) continue;
                    float p  = fmaxf(acc[i][j][h * 2 + e], 1e-3f);
                    float s2 = log1pf(1.f / p + od);
                    float mu = logf(p) - 0.5f * s2;
                    float lx = logf(Xr[gn]);
                    float d  = lx - mu;
                    lsum += (double)(-lx - 0.5f * logf(s2) - 0.5f * LOG2PI_ - d * d / (2.f * s2));
                }
            }
        }
    }

    __shared__ double red[256];
    red[tid] = lsum;
    __syncthreads();
#pragma unroll
    for (int o = 128; o > 0; o >>= 1) {
        if (tid < o) red[tid] += red[tid + o];
        __syncthreads();
    }
    if (tid == 0) {
        int blin = (blockIdx.z * gridDim.y + blockIdx.y) * gridDim.x + blockIdx.x;
        g_part[slotBase + blin] = red[0];
    }
}

// ============================================================
__device__ __forceinline__ float negbin_lp(float k, float rate, float od) {
    float rnb = 1.f / od;
    float lq  = -logf(1.f + od * rate);
    float lp  = logf(od * rate) + lq;
    return lgammaf(k + rnb) - lgammaf(rnb) - lgammaf(k + 1.f) + rnb * lq + k * lp;
}

__global__ void k_misc(const float* __restrict__ inf, const float* __restrict__ crt,
                       const float* __restrict__ crr, const float* __restrict__ Rtr,
                       const float* __restrict__ caseD, const float* __restrict__ deathD,
                       const float* __restrict__ codp, const float* __restrict__ dodp,
                       const float* __restrict__ dsp, int slotBase) {
    __shared__ double red[256];
    int tid  = threadIdx.x;
    int w    = (blockIdx.x * blockDim.x + tid) >> 5;
    int lane = tid & 31;
    double lsum = 0.0;
    if (w < T_ * R_) {
        int t = w / R_, r = w - t * R_;
        const float* row = inf + (size_t)w * S_;
        float ssum = 0.f;
        for (int i = lane; i < S_; i += 32) ssum += row[i];
#pragma unroll
        for (int o = 16; o > 0; o >>= 1) ssum += __shfl_xor_sync(0xffffffffu, ssum, o);
        if (lane == 0) {
            lsum += (double)negbin_lp(caseD[w], ssum * crt[t] * crr[r], *codp);
            lsum += (double)negbin_lp(deathD[w], ssum * DEATH_RATE_, *dodp);
            if (t >= 1) {
                float ds = *dsp;
                float lx = logf(Rtr[w] / Rtr[w - R_]);
                lsum += (double)(-lx - logf(ds) - 0.5f * LOG2PI_ - lx * lx / (2.f * ds * ds));
            }
        }
    }
    red[tid] = lsum;
    __syncthreads();
#pragma unroll
    for (int o = 128; o > 0; o >>= 1) {
        if (tid < o) red[tid] += red[tid + o];
        __syncthreads();
    }
    if (tid == 0) g_part[slotBase + blockIdx.x] = red[0];
}

// ============================================================
__device__ __forceinline__ float blkred_f(float v, float* red, int tid) {
    red[tid] = v;
    __syncthreads();
#pragma unroll
    for (int o = 128; o > 0; o >>= 1) {
        if (tid < o) red[tid] += red[tid + o];
        __syncthreads();
    }
    float r = red[0];
    __syncthreads();
    return r;
}

__global__ void k_strain(const float* __restrict__ inf, const float* __restrict__ strain,
                         const float* __restrict__ sampleM, int slotBase) {
    __shared__ float w[R_];
    __shared__ float red[256];
    int b = blockIdx.x;
    int t = b / RC_, c = b - t * RC_;
    int tid = threadIdx.x;
    for (int i = tid; i < R_; i += 256) w[i] = sampleM[c * R_ + i];
    __syncthreads();

    int s0 = tid, s1 = tid + 256;
    bool v1 = (s1 < S_);
    float c0 = 1e-6f, c1 = 1e-6f;
    const float* It = inf + (size_t)t * R_ * S_;
    for (int r = 0; r < R_; r++) {
        float wv = w[r];
        if (wv != 0.f) {
            const float* rowp = It + (size_t)r * S_;
            c0 += wv * rowp[s0];
            if (v1) c1 += wv * rowp[s1];
        }
    }
    float total = blkred_f(c0 + (v1 ? c1 : 0.f), red, tid);

    const float* sd = strain + (size_t)b * S_;
    float sd0 = sd[s0], sd1 = v1 ? sd[s1] : 0.f;
    float lc0 = logf(c0);
    float lc1 = v1 ? logf(c1) : 0.f;

    float slc = blkred_f(sd0 * lc0 + sd1 * lc1, red, tid);
    float slg = blkred_f(lgammaf(sd0 + 1.f) + (v1 ? lgammaf(sd1 + 1.f) : 0.f), red, tid);
    float n   = blkred_f(sd0 + sd1, red, tid);

    if (tid == 0)
        g_part[slotBase + b] = (double)(lgammaf(n + 1.f) - slg + slc - n * logf(total));
}

// ============================================================
__global__ void k_final(float* __restrict__ out) {
    __shared__ double red[256];
    int tid = threadIdx.x;
    double s = 0.0;
    for (int i = tid; i < NSLOTS; i += 256) s += g_part[i];
    red[tid] = s;
    __syncthreads();
#pragma unroll
    for (int o = 128; o > 0; o >>= 1) {
        if (tid < o) red[tid] += red[tid + o];
        __syncthreads();
    }
    if (tid == 0) out[0] = (float)red[0];
}

// ============================================================
extern "C" void kernel_launch(void* const* d_in, const int* in_sizes, int n_in,
                              void* d_out, int out_size) {
    const float* inf    = (const float*)d_in[0];
    const float* crt    = (const float*)d_in[1];
    const float* crr    = (const float*)d_in[2];
    const float* R0p    = (const float*)d_in[3];
    const float* Rs     = (const float*)d_in[4];
    const float* Rtr    = (const float*)d_in[5];
    const float* trate  = (const float*)d_in[6];
    const float* mrp    = (const float*)d_in[7];
    const float* iodp   = (const float*)d_in[8];
    const float* codp   = (const float*)d_in[9];
    const float* dodp   = (const float*)d_in[10];
    const float* dsp    = (const float*)d_in[11];
    const float* td     = (const float*)d_in[12];
    const float* caseD  = (const float*)d_in[13];
    const float* deathD = (const float*)d_in[14];
    const float* strain = (const float*)d_in[15];
    const float* sampM  = (const float*)d_in[16];
    const float* mm     = (const float*)d_in[17];
    float* out = (float*)d_out;

    k_init<<<(NSLOTS + 255) / 256, 256>>>();
    k_prep<<<(KPAD * KPAD + 255) / 256, 256>>>(td, trate, mm, mrp);

    dim3 g1((S_ + BN - 1) / BN, (R_ + BM - 1) / BM, T_ - 1);   // (4, 5, 99)
    k_gemm1<<<g1, GT>>>(inf, Rtr, Rs, R0p);

    dim3 g2(4, 3, T_ - 1);                                      // 512/128 n, 384/128 m
    k_gemm2m<<<g2, 256>>>(inf, iodp, SLOT_GEMM2);

    k_misc<<<(T_ * R_ * 32 + 255) / 256, 256>>>(inf, crt, crr, Rtr, caseD, deathD,
                                                codp, dodp, dsp, SLOT_MISC);
    k_strain<<<T_ * RC_, 256>>>(inf, strain, sampM, SLOT_STRAIN);
    k_final<<<1, 256>>>(out);
}

// round 17
// speedup vs baseline: 1.7390x; 1.2715x over previous
#include <cuda_runtime.h>
#include <cuda_bf16.h>
#include <cstdint>

#define T_   100
#define R_   300
#define S_   500
#define P_   8
#define RC_  50
#define LOG2PI_ 1.8378770664093453f
#define DEATH_RATE_ 0.02f

#define MPAD 384     // padded R for MMA m-tiles (3 x 128)
#define KPAD 512     // padded S/K stride (bf16 rows 1024B)

// ---- gemm1 (SIMT) tiling ----
#define BM 64
#define BN 128
#define BK 16
#define GT 128

// ---- gemm2 (mma.sync) smem tiling ----
#define KC   32      // k-chunk per smem stage
#define APAD 40      // padded cols per chunk row (80B stride: 16B-mult, bank-spread)
#define BUFB (128 * APAD * 2)   // bytes per buffer per tile

#define NSLOTS 16384
#define SLOT_GEMM2  0      // 1188 blocks
#define SLOT_MISC   4096   // 3750 blocks
#define SLOT_STRAIN 8192   // 5000 blocks

// ---- scratch (device globals; zero-initialized at load; no allocation) ----
__device__ float          g_transitT[R_ * R_];                         // transitT[R][r]
__device__ __nv_bfloat16  g_pred1b[(size_t)(T_ - 1) * MPAD * KPAD];    // 39MB, pads stay 0
__device__ __nv_bfloat16  g_mutB[KPAD * KPAD];                         // B[n][k] = mut[k][n]
__device__ double         g_part[NSLOTS];

// ===================== ptx helpers =====================
__device__ __forceinline__ unsigned long long pack_dup_f32x2(float v) {
    unsigned long long d; unsigned int u = __float_as_uint(v);
    asm("mov.b64 %0, {%1, %1};" : "=l"(d) : "r"(u)); return d;
}
__device__ __forceinline__ void fma_f32x2(unsigned long long& acc,
                                          unsigned long long a, unsigned long long b) {
    asm("fma.rn.f32x2 %0, %1, %2, %0;" : "+l"(acc) : "l"(a), "l"(b));
}
__device__ __forceinline__ void cp_async16(void* smem_dst, const void* gsrc, int src_bytes) {
    unsigned int saddr = (unsigned int)__cvta_generic_to_shared(smem_dst);
    asm volatile("cp.async.cg.shared.global [%0], [%1], 16, %2;"
                 :: "r"(saddr), "l"(gsrc), "r"(src_bytes));
}
#define CP_COMMIT() asm volatile("cp.async.commit_group;" ::: "memory")
#define CP_WAIT0()  asm volatile("cp.async.wait_group 0;" ::: "memory")
#define CP_WAIT1()  asm volatile("cp.async.wait_group 1;" ::: "memory")

// mma.sync m16n8k16 row.col f32 += bf16*bf16 (sm_80+, valid on plain sm_103 target)
__device__ __forceinline__ void mma16816(float* d, const uint32_t* a, const uint32_t* b) {
    asm volatile("mma.sync.aligned.m16n8k16.row.col.f32.bf16.bf16.f32 "
                 "{%0,%1,%2,%3}, {%4,%5,%6,%7}, {%8,%9}, {%0,%1,%2,%3};"
                 : "+f"(d[0]), "+f"(d[1]), "+f"(d[2]), "+f"(d[3])
                 : "r"(a[0]), "r"(a[1]), "r"(a[2]), "r"(a[3]), "r"(b[0]), "r"(b[1]));
}
__device__ __forceinline__ void ldsm4(uint32_t& r0, uint32_t& r1, uint32_t& r2, uint32_t& r3,
                                      uint32_t addr) {
    asm volatile("ldmatrix.sync.aligned.m8n8.x4.shared.b16 {%0,%1,%2,%3}, [%4];"
                 : "=r"(r0), "=r"(r1), "=r"(r2), "=r"(r3) : "r"(addr));
}

// ============================================================
__global__ void k_init() {
    int i = blockIdx.x * blockDim.x + threadIdx.x;
    if (i < NSLOTS) g_part[i] = 0.0;
}

__global__ void k_prep(const float* __restrict__ td, const float* __restrict__ tr,
                       const float* __restrict__ mm, const float* __restrict__ mrp) {
    int i = blockIdx.x * blockDim.x + threadIdx.x;
    if (i < R_ * R_) {
        int Rr = i / R_, r = i - Rr * R_;
        float a = 0.f;
#pragma unroll
        for (int p = 0; p < P_; p++)
            a += td[((size_t)r * R_ + Rr) * P_ + p] * tr[p];
        g_transitT[i] = a;
    }
    if (i < KPAD * KPAD) {    // B[n][k] = mut[k][n], bf16, zero-padded
        int n = i >> 9, k = i & 511;
        float v = 0.f;
        if (n < S_ && k < S_)
            v = (k == n ? 1.f : 0.f) + (*mrp) * mm[k * S_ + n];
        g_mutB[i] = __float2bfloat16(v);
    }
}

// ============================================================
// GEMM1 (SIMT f32x2): pred1[t,m,s] = [sum_r transitT[m,r]*Rtr[t,r]*inf[t,r,s]] * R0*Rs[s]
// Output: bf16 into g_pred1b with KPAD stride; pad cols 500..511 written as 0.
__device__ __forceinline__ void mm_tile(const float (*As)[BM + 4], const float (*Bs)[BN],
                                        int tx, int ty, unsigned long long acc2[4][8]) {
#pragma unroll
    for (int k = 0; k < BK; k++) {
        ulonglong2 ap0 = *(const ulonglong2*)&As[k][ty * 8];
        ulonglong2 ap1 = *(const ulonglong2*)&As[k][ty * 8 + 4];
        float4 b0 = *(const float4*)&Bs[k][tx * 8];
        float4 b1 = *(const float4*)&Bs[k][tx * 8 + 4];
        unsigned long long ap[4] = {ap0.x, ap0.y, ap1.x, ap1.y};
        unsigned long long bb[8] = {pack_dup_f32x2(b0.x), pack_dup_f32x2(b0.y),
                                    pack_dup_f32x2(b0.z), pack_dup_f32x2(b0.w),
                                    pack_dup_f32x2(b1.x), pack_dup_f32x2(b1.y),
                                    pack_dup_f32x2(b1.z), pack_dup_f32x2(b1.w)};
#pragma unroll
        for (int ip = 0; ip < 4; ip++)
#pragma unroll
            for (int j = 0; j < 8; j++) fma_f32x2(acc2[ip][j], ap[ip], bb[j]);
    }
}

__device__ __forceinline__ void b_tile_cp(float (*dst)[BN], const float* __restrict__ base,
                                          int ld, int kb, int rowLimit, int n0, int tid) {
#pragma unroll
    for (int i = 0; i < 4; i++) {
        int chunk = i * GT + tid;
        int kk = chunk >> 5;
        int cc = (chunk & 31) * 4;
        int gk = kb + kk, gn = n0 + cc;
        bool ok = (gk < rowLimit) && (gn + 3 < S_);
        cp_async16(&dst[kk][cc], ok ? &base[(size_t)gk * ld + gn] : base, ok ? 16 : 0);
    }
}

__global__ __launch_bounds__(GT, 4) void k_gemm1(const float* __restrict__ inf,
                                                 const float* __restrict__ Rtr,
                                                 const float* __restrict__ Rs,
                                                 const float* __restrict__ R0p) {
    int t  = blockIdx.z;
    int m0 = blockIdx.y * BM;
    int n0 = blockIdx.x * BN;
    __shared__ __align__(16) float As[2][BK][BM + 4];
    __shared__ __align__(16) float Bs[2][BK][BN];
    int tid = threadIdx.x;
    int tx = tid & 15, ty = tid >> 4;
    unsigned long long acc2[4][8];
#pragma unroll
    for (int i = 0; i < 4; i++)
#pragma unroll
        for (int j = 0; j < 8; j++) acc2[i][j] = 0ULL;

    const float* Bt   = inf + (size_t)t * R_ * S_;
    const float* RtrT = Rtr + t * R_;
    const int lkA = tid & 15, lmA = tid >> 4;   // m strides by 8

    float ra[8];
    b_tile_cp(Bs[0], Bt, S_, 0, R_, n0, tid);
    CP_COMMIT();
    {
        float rt = (lkA < R_) ? RtrT[lkA] : 0.f;
#pragma unroll
        for (int i = 0; i < 8; i++) {
            int gm = m0 + lmA + i * 8;
            As[0][lkA][lmA + i * 8] = (gm < R_ && lkA < R_) ? g_transitT[gm * R_ + lkA] * rt : 0.f;
        }
    }
    CP_WAIT0();
    __syncthreads();

    const int NT = (R_ + BK - 1) / BK;   // 19
    for (int it = 0; it < NT; it++) {
        int buf = it & 1;
        bool has = (it + 1) < NT;
        if (has) {
            int kb = (it + 1) * BK;
            b_tile_cp(Bs[buf ^ 1], Bt, S_, kb, R_, n0, tid);
            CP_COMMIT();
            int gk = kb + lkA;
            float rt = (gk < R_) ? RtrT[gk] : 0.f;
#pragma unroll
            for (int i = 0; i < 8; i++) {
                int gm = m0 + lmA + i * 8;
                ra[i] = (gm < R_ && gk < R_) ? g_transitT[gm * R_ + gk] * rt : 0.f;
            }
        }
        mm_tile(As[buf], Bs[buf], tx, ty, acc2);
        if (has) {
#pragma unroll
            for (int i = 0; i < 8; i++) As[buf ^ 1][lkA][lmA + i * 8] = ra[i];
            CP_WAIT0();
            __syncthreads();
        }
    }

    // bf16 store, scaled by R0*Rs[n]; pad cols (>=500) get 0 (rs=0, acc=0)
    const float R0 = *R0p;
    __nv_bfloat16* C = g_pred1b + (size_t)t * MPAD * KPAD;
    int gnb = n0 + tx * 8;
    float4 rs[2];
#pragma unroll
    for (int q = 0; q < 2; q++)
        rs[q] = (gnb + q * 4 < S_) ? *(const float4*)&Rs[gnb + q * 4]
                                   : make_float4(0.f, 0.f, 0.f, 0.f);
#pragma unroll
    for (int ip = 0; ip < 4; ip++) {
#pragma unroll
        for (int h = 0; h < 2; h++) {
            int gm = m0 + ty * 8 + 2 * ip + h;
            if (gm >= R_) continue;
            __nv_bfloat16* Crow = C + (size_t)gm * KPAD;
#pragma unroll
            for (int q = 0; q < 2; q++) {
                int gn = gnb + q * 4;      // < 512 always
                float2 f0 = *(float2*)&acc2[ip][q * 4 + 0];
                float2 f1 = *(float2*)&acc2[ip][q * 4 + 1];
                float2 f2 = *(float2*)&acc2[ip][q * 4 + 2];
                float2 f3 = *(float2*)&acc2[ip][q * 4 + 3];
                float4 v = h ? make_float4(f0.y, f1.y, f2.y, f3.y)
                             : make_float4(f0.x, f1.x, f2.x, f3.x);
                v.x *= R0 * rs[q].x; v.y *= R0 * rs[q].y;
                v.z *= R0 * rs[q].z; v.w *= R0 * rs[q].w;
                __nv_bfloat162 b01 = __floats2bfloat162_rn(v.x, v.y);
                __nv_bfloat162 b23 = __floats2bfloat162_rn(v.z, v.w);
                uint2 pk;
                pk.x = *(unsigned int*)&b01;
                pk.y = *(unsigned int*)&b23;
                *(uint2*)(Crow + gn) = pk;   // 8B-aligned (gn%4==0, row 1024B)
            }
        }
    }
}

// ============================================================
// GEMM2 via mma.sync with smem staging + ldmatrix.
// D[128,128] per block; A = g_pred1b, B = g_mutB ([n][k], k-contiguous).
// Double-buffered KC=32 chunks via cp.async (no bounds checks: gmem pre-padded).
// Fused RelaxedPoisson LL epilogue from accumulator registers.
__global__ __launch_bounds__(256, 2) void k_gemm2m(const float* __restrict__ inf,
                                                   const float* __restrict__ iodp,
                                                   int slotBase) {
    __shared__ __align__(16) __nv_bfloat16 As[2][128][APAD];
    __shared__ __align__(16) __nv_bfloat16 Bs[2][128][APAD];
    __shared__ double red[256];

    const int t  = blockIdx.z;
    const int m0 = blockIdx.y * 128;
    const int n0 = blockIdx.x * 128;
    const int tid = threadIdx.x, wid = tid >> 5, lane = tid & 31;
    const int wm = (wid & 3) * 32;     // warp m offset in tile
    const int wn = (wid >> 2) * 64;    // warp n offset in tile
    const int gid = lane >> 2, qid = lane & 3;

    const __nv_bfloat16* Abase = g_pred1b + ((size_t)t * MPAD + m0) * KPAD;
    const __nv_bfloat16* Bbase = g_mutB + (size_t)n0 * KPAD;

    // copy coords: 512 16B-chunks per tile, 2 per thread; row 0..127, c = (id&3)*8 elems
    const int cr0 = tid >> 2,          cc0 = (tid & 3) * 8;
    const int cr1 = (tid + 256) >> 2,  cc1 = ((tid + 256) & 3) * 8;

    // ldmatrix per-lane base addresses (byte offsets; row stride 80B = 16B-mult)
    const uint32_t aSm = (uint32_t)__cvta_generic_to_shared(&As[0][0][0]);
    const uint32_t bSm = (uint32_t)__cvta_generic_to_shared(&Bs[0][0][0]);
    const int L = lane;
    const uint32_t aAddr0 = aSm + (uint32_t)(wm + (L & 15)) * (APAD * 2)
                                + (uint32_t)(((L >> 4) << 3) * 2);
    const uint32_t bAddr0 = bSm + (uint32_t)(wn + (L & 7) + ((L >> 4) << 3)) * (APAD * 2)
                                + (uint32_t)((((L >> 3) & 1) << 3) * 2);

    float acc[2][8][4];
#pragma unroll
    for (int i = 0; i < 2; i++)
#pragma unroll
        for (int j = 0; j < 8; j++)
#pragma unroll
            for (int c = 0; c < 4; c++) acc[i][j][c] = 0.f;

    // ---- preload chunk 0 ----
    {
        cp_async16(&As[0][cr0][cc0], Abase + (size_t)cr0 * KPAD + cc0, 16);
        cp_async16(&Bs[0][cr0][cc0], Bbase + (size_t)cr0 * KPAD + cc0, 16);
        cp_async16(&As[0][cr1][cc1], Abase + (size_t)cr1 * KPAD + cc1, 16);
        cp_async16(&Bs[0][cr1][cc1], Bbase + (size_t)cr1 * KPAD + cc1, 16);
        CP_COMMIT();
    }

    const int NC = KPAD / KC;   // 16
    for (int c = 0; c < NC; c++) {
        int buf = c & 1;
        bool has = (c + 1) < NC;
        if (has) {
            int kb = (c + 1) * KC;
            cp_async16(&As[buf ^ 1][cr0][cc0], Abase + (size_t)cr0 * KPAD + kb + cc0, 16);
            cp_async16(&Bs[buf ^ 1][cr0][cc0], Bbase + (size_t)cr0 * KPAD + kb + cc0, 16);
            cp_async16(&As[buf ^ 1][cr1][cc1], Abase + (size_t)cr1 * KPAD + kb + cc1, 16);
            cp_async16(&Bs[buf ^ 1][cr1][cc1], Bbase + (size_t)cr1 * KPAD + kb + cc1, 16);
            CP_COMMIT();
            CP_WAIT1();
        } else {
            CP_WAIT0();
        }
        __syncthreads();

        uint32_t bufOff = (uint32_t)buf * BUFB;
#pragma unroll
        for (int s = 0; s < 2; s++) {       // two k=16 steps per KC=32 chunk
            uint32_t a[2][4], b[8][2];
#pragma unroll
            for (int i = 0; i < 2; i++)
                ldsm4(a[i][0], a[i][1], a[i][2], a[i][3],
                      aAddr0 + bufOff + (uint32_t)(i * 16 * APAD * 2) + (uint32_t)(s * 32));
#pragma unroll
            for (int jp = 0; jp < 4; jp++) {
                uint32_t r0, r1, r2, r3;
                ldsm4(r0, r1, r2, r3,
                      bAddr0 + bufOff + (uint32_t)(jp * 16 * APAD * 2) + (uint32_t)(s * 32));
                b[2 * jp][0] = r0; b[2 * jp][1] = r1;
                b[2 * jp + 1][0] = r2; b[2 * jp + 1][1] = r3;
            }
#pragma unroll
            for (int i = 0; i < 2; i++)
#pragma unroll
                for (int j = 0; j < 8; j++) mma16816(acc[i][j], a[i], b[j]);
        }
        __syncthreads();
    }

    // Epilogue: lane owns rows m0+wm+i*16+gid(+8), cols n0+wn+j*8+qid*2(+1)
    const float od = *iodp;
    const float* X = inf + (size_t)(t + 1) * R_ * S_;
    double lsum = 0.0;
#pragma unroll
    for (int i = 0; i < 2; i++) {
#pragma unroll
        for (int h = 0; h < 2; h++) {
            int gm = m0 + wm + i * 16 + gid + h * 8;
            if (gm >= R_) continue;
            const float* Xr = X + (size_t)gm * S_;
#pragma unroll
            for (int j = 0; j < 8; j++) {
                int col0 = n0 + wn + j * 8 + qid * 2;
#pragma unroll
                for (int e = 0; e < 2; e++) {
                    int gn = col0 + e;
                    if (gn >= S_) continue;
                    float p  = fmaxf(acc[i][j][h * 2 + e], 1e-3f);
                    float s2 = log1pf(1.f / p + od);
                    float mu = logf(p) - 0.5f * s2;
                    float lx = logf(Xr[gn]);
                    float d  = lx - mu;
                    lsum += (double)(-lx - 0.5f * logf(s2) - 0.5f * LOG2PI_ - d * d / (2.f * s2));
                }
            }
        }
    }

    red[tid] = lsum;
    __syncthreads();
#pragma unroll
    for (int o = 128; o > 0; o >>= 1) {
        if (tid < o) red[tid] += red[tid + o];
        __syncthreads();
    }
    if (tid == 0) {
        int blin = (blockIdx.z * gridDim.y + blockIdx.y) * gridDim.x + blockIdx.x;
        g_part[slotBase + blin] = red[0];
    }
}

// ============================================================
__device__ __forceinline__ float negbin_lp(float k, float rate, float od) {
    float rnb = 1.f / od;
    float lq  = -logf(1.f + od * rate);
    float lp  = logf(od * rate) + lq;
    return lgammaf(k + rnb) - lgammaf(rnb) - lgammaf(k + 1.f) + rnb * lq + k * lp;
}

__global__ void k_misc(const float* __restrict__ inf, const float* __restrict__ crt,
                       const float* __restrict__ crr, const float* __restrict__ Rtr,
                       const float* __restrict__ caseD, const float* __restrict__ deathD,
                       const float* __restrict__ codp, const float* __restrict__ dodp,
                       const float* __restrict__ dsp, int slotBase) {
    __shared__ double red[256];
    int tid  = threadIdx.x;
    int w    = (blockIdx.x * blockDim.x + tid) >> 5;
    int lane = tid & 31;
    double lsum = 0.0;
    if (w < T_ * R_) {
        int t = w / R_, r = w - t * R_;
        const float* row = inf + (size_t)w * S_;
        float ssum = 0.f;
        for (int i = lane; i < S_; i += 32) ssum += row[i];
#pragma unroll
        for (int o = 16; o > 0; o >>= 1) ssum += __shfl_xor_sync(0xffffffffu, ssum, o);
        if (lane == 0) {
            lsum += (double)negbin_lp(caseD[w], ssum * crt[t] * crr[r], *codp);
            lsum += (double)negbin_lp(deathD[w], ssum * DEATH_RATE_, *dodp);
            if (t >= 1) {
                float ds = *dsp;
                float lx = logf(Rtr[w] / Rtr[w - R_]);
                lsum += (double)(-lx - logf(ds) - 0.5f * LOG2PI_ - lx * lx / (2.f * ds * ds));
            }
        }
    }
    red[tid] = lsum;
    __syncthreads();
#pragma unroll
    for (int o = 128; o > 0; o >>= 1) {
        if (tid < o) red[tid] += red[tid + o];
        __syncthreads();
    }
    if (tid == 0) g_part[slotBase + blockIdx.x] = red[0];
}

// ============================================================
__device__ __forceinline__ float blkred_f(float v, float* red, int tid) {
    red[tid] = v;
    __syncthreads();
#pragma unroll
    for (int o = 128; o > 0; o >>= 1) {
        if (tid < o) red[tid] += red[tid + o];
        __syncthreads();
    }
    float r = red[0];
    __syncthreads();
    return r;
}

__global__ void k_strain(const float* __restrict__ inf, const float* __restrict__ strain,
                         const float* __restrict__ sampleM, int slotBase) {
    __shared__ float w[R_];
    __shared__ float red[256];
    int b = blockIdx.x;
    int t = b / RC_, c = b - t * RC_;
    int tid = threadIdx.x;
    for (int i = tid; i < R_; i += 256) w[i] = sampleM[c * R_ + i];
    __syncthreads();

    int s0 = tid, s1 = tid + 256;
    bool v1 = (s1 < S_);
    float c0 = 1e-6f, c1 = 1e-6f;
    const float* It = inf + (size_t)t * R_ * S_;
    for (int r = 0; r < R_; r++) {
        float wv = w[r];
        if (wv != 0.f) {
            const float* rowp = It + (size_t)r * S_;
            c0 += wv * rowp[s0];
            if (v1) c1 += wv * rowp[s1];
        }
    }
    float total = blkred_f(c0 + (v1 ? c1 : 0.f), red, tid);

    const float* sd = strain + (size_t)b * S_;
    float sd0 = sd[s0], sd1 = v1 ? sd[s1] : 0.f;
    float lc0 = logf(c0);
    float lc1 = v1 ? logf(c1) : 0.f;

    float slc = blkred_f(sd0 * lc0 + sd1 * lc1, red, tid);
    float slg = blkred_f(lgammaf(sd0 + 1.f) + (v1 ? lgammaf(sd1 + 1.f) : 0.f), red, tid);
    float n   = blkred_f(sd0 + sd1, red, tid);

    if (tid == 0)
        g_part[slotBase + b] = (double)(lgammaf(n + 1.f) - slg + slc - n * logf(total));
}

// ============================================================
__global__ void k_final(float* __restrict__ out) {
    __shared__ double red[256];
    int tid = threadIdx.x;
    double s = 0.0;
    for (int i = tid; i < NSLOTS; i += 256) s += g_part[i];
    red[tid] = s;
    __syncthreads();
#pragma unroll
    for (int o = 128; o > 0; o >>= 1) {
        if (tid < o) red[tid] += red[tid + o];
        __syncthreads();
    }
    if (tid == 0) out[0] = (float)red[0];
}

// ============================================================
extern "C" void kernel_launch(void* const* d_in, const int* in_sizes, int n_in,
                              void* d_out, int out_size) {
    const float* inf    = (const float*)d_in[0];
    const float* crt    = (const float*)d_in[1];
    const float* crr    = (const float*)d_in[2];
    const float* R0p    = (const float*)d_in[3];
    const float* Rs     = (const float*)d_in[4];
    const float* Rtr    = (const float*)d_in[5];
    const float* trate  = (const float*)d_in[6];
    const float* mrp    = (const float*)d_in[7];
    const float* iodp   = (const float*)d_in[8];
    const float* codp   = (const float*)d_in[9];
    const float* dodp   = (const float*)d_in[10];
    const float* dsp    = (const float*)d_in[11];
    const float* td     = (const float*)d_in[12];
    const float* caseD  = (const float*)d_in[13];
    const float* deathD = (const float*)d_in[14];
    const float* strain = (const float*)d_in[15];
    const float* sampM  = (const float*)d_in[16];
    const float* mm     = (const float*)d_in[17];
    float* out = (float*)d_out;

    k_init<<<(NSLOTS + 255) / 256, 256>>>();
    k_prep<<<(KPAD * KPAD + 255) / 256, 256>>>(td, trate, mm, mrp);

    dim3 g1((S_ + BN - 1) / BN, (R_ + BM - 1) / BM, T_ - 1);   // (4, 5, 99)
    k_gemm1<<<g1, GT>>>(inf, Rtr, Rs, R0p);

    dim3 g2(4, 3, T_ - 1);                                      // 512/128 n, 384/128 m
    k_gemm2m<<<g2, 256>>>(inf, iodp, SLOT_GEMM2);

    k_misc<<<(T_ * R_ * 32 + 255) / 256, 256>>>(inf, crt, crr, Rtr, caseD, deathD,
                                                codp, dodp, dsp, SLOT_MISC);
    k_strain<<<T_ * RC_, 256>>>(inf, strain, sampM, SLOT_STRAIN);
    k_final<<<1, 256>>>(out);
}